// round 11
// baseline (speedup 1.0000x reference)
#include <cuda_runtime.h>
#include <cstdint>

// 3x3 conv, stride 1, pad 1, NCHW fp32. B=8, CIN=COUT=16, H=W=1024.
// v5: compute loop identical to v3/v4. Staging rewritten division-free:
//  - input: one warp per ci, per-row LDG.128 (lanes 0-15) + halo lanes 16/17
//  - weights: thread t <-> (ci,co) pair, 9 float2 writes, no div/mod
// Tile 8x64, NCO=4, two 8-ci halves, 3 blocks/SM (24 warps).

#define CIN   16
#define COUT  16
#define Hh    1024
#define Ww    1024
#define Bb    8

#define TH    8           // output rows per block
#define TW    64          // output cols per block
#define VEC   8           // pixels per thread
#define NCO   4           // couts per thread group
#define THREADS 256

#define HALF_CI  8
#define IN_ROWS  (TH + 2)         // 10
#define PITCH    72               // 288B rows, 16B multiple for LDS.128
#define SIN_FLOATS (HALF_CI * IN_ROWS * PITCH)   // 5760 (23040 B)
#define SW_FLOAT2  (CIN * COUT * 9)              // 2304  (18432 B)

typedef unsigned long long ull;

__device__ __forceinline__ void fma2(ull& d, ull a, ull b) {
    asm("fma.rn.f32x2 %0, %1, %2, %0;" : "+l"(d) : "l"(a), "l"(b));
}
__device__ __forceinline__ ull pack2(float lo, float hi) {
    ull r;
    asm("mov.b64 %0, {%1, %2};" : "=l"(r) : "f"(lo), "f"(hi));
    return r;
}
__device__ __forceinline__ void unpack2(ull v, float& lo, float& hi) {
    asm("mov.b64 {%0, %1}, %2;" : "=f"(lo), "=f"(hi) : "l"(v));
}

union U4 { float4 f; ull u[2]; };
union U2 { float2 f; ull u; };

__global__ __launch_bounds__(THREADS, 3)
void conv3x3_kernel(const float* __restrict__ x,
                    const float* __restrict__ w,
                    float* __restrict__ out)
{
    __shared__ float  s_in[SIN_FLOATS];       // [ci_local][row][PITCH], lc = gx-x_base+1
    __shared__ float2 s_w[SW_FLOAT2];         // [ci][co][9], (w,w) duplicated

    const int t    = threadIdx.x;
    const int wid  = t >> 5;
    const int lane = t & 31;
    const int bx = blockIdx.x;       // 0..15   -> x_base
    const int by = blockIdx.y;       // 0..127  -> y_base
    const int b  = blockIdx.z;       // batch
    const int x_base = bx * TW;
    const int y_base = by * TH;

    // ---- stage all weights once: thread t <-> (ci,co), no div/mod ----
    {
        int ci = t >> 4;             // 0..15
        int co = t & 15;             // 0..15
        const float* wsrc = w + (co * CIN + ci) * 9;
        float2* wdst = &s_w[(ci * COUT + co) * 9];
        #pragma unroll
        for (int k = 0; k < 9; k++) {
            float wv = wsrc[k];
            wdst[k] = make_float2(wv, wv);
        }
    }

    // ---- thread mapping for compute ----
    const int grp = t >> 6;          // 0..3 -> cout quarter
    const int p   = t & 63;
    const int ty  = p >> 3;          // 0..7 output row in tile
    const int xg  = p & 7;           // 0..7 x-group
    const int x0  = xg * VEC;        // window lc = x0 .. x0+9 (16B-aligned base)
    const int co0 = grp * NCO;

    ull acc[NCO][4];
    #pragma unroll
    for (int c = 0; c < NCO; c++)
        #pragma unroll
        for (int q = 0; q < 4; q++) acc[c][q] = 0ull;

    #pragma unroll 1
    for (int half = 0; half < 2; half++) {
        // ---- stage this half: warp wid stages ci = half*8+wid (10 rows x 66) ----
        {
            const int ci = half * HALF_CI + wid;
            const float* src = x + ((size_t)b * CIN + ci) * Hh * Ww;
            float* dst = &s_in[wid * IN_ROWS * PITCH];
            #pragma unroll 1
            for (int r = 0; r < IN_ROWS; r++) {
                const int gy = y_base + r - 1;
                const bool vrow = (unsigned)gy < (unsigned)Hh;
                const float* srow = src + (size_t)gy * Ww + x_base;
                float* drow = dst + r * PITCH;
                if (lane < 16) {
                    float4 v = vrow ? *(const float4*)(srow + 4 * lane)
                                    : make_float4(0.f, 0.f, 0.f, 0.f);
                    const int o = 4 * lane + 1;        // lc = gx - x_base + 1
                    drow[o + 0] = v.x;
                    drow[o + 1] = v.y;
                    drow[o + 2] = v.z;
                    drow[o + 3] = v.w;
                } else if (lane == 16) {
                    drow[0]  = (vrow && x_base > 0)        ? srow[-1] : 0.f;
                } else if (lane == 17) {
                    drow[65] = (vrow && x_base + TW < Ww)  ? srow[TW] : 0.f;
                }
            }
        }
        __syncthreads();

        // ---- compute over this half's 8 ci (unchanged from v3/v4) ----
        #pragma unroll 1
        for (int cil = 0; cil < HALF_CI; cil++) {
            const float* in_ci = &s_in[(cil * IN_ROWS + ty) * PITCH + x0];
            const float2* w_ci = &s_w[((half * HALF_CI + cil) * COUT + co0) * 9];
            #pragma unroll
            for (int ry = 0; ry < 3; ry++) {
                const float* row = in_ci + ry * PITCH;
                U4 va, vb; U2 vc;
                va.f = *(const float4*)(row);        // v0..v3
                vb.f = *(const float4*)(row + 4);    // v4..v7
                vc.f = *(const float2*)(row + 8);    // v8,v9
                ull pr[9];
                pr[0] = va.u[0];                     // (v0,v1)
                pr[2] = va.u[1];                     // (v2,v3)
                pr[4] = vb.u[0];                     // (v4,v5)
                pr[6] = vb.u[1];                     // (v6,v7)
                pr[8] = vc.u;                        // (v8,v9)
                pr[1] = pack2(va.f.y, va.f.z);       // (v1,v2)
                pr[3] = pack2(va.f.w, vb.f.x);       // (v3,v4)
                pr[5] = pack2(vb.f.y, vb.f.z);       // (v5,v6)
                pr[7] = pack2(vb.f.w, vc.f.x);       // (v7,v8)
                #pragma unroll
                for (int c = 0; c < NCO; c++) {
                    const ull* wp = (const ull*)&w_ci[c * 9 + ry * 3];
                    #pragma unroll
                    for (int kx = 0; kx < 3; kx++) {
                        ull w2 = wp[kx];
                        #pragma unroll
                        for (int q = 0; q < 4; q++)
                            fma2(acc[c][q], pr[kx + 2 * q], w2);
                    }
                }
            }
        }
        __syncthreads();   // protect s_in before next half restages
    }

    // ---- write back: 2x float4 per cout ----
    const int oy = y_base + ty;
    const int ox = x_base + x0;
    #pragma unroll
    for (int c = 0; c < NCO; c++) {
        float* op = &out[(((size_t)b * COUT + (co0 + c)) * Hh + oy) * Ww + ox];
        float r0, r1, r2, r3, r4, r5, r6, r7;
        unpack2(acc[c][0], r0, r1);
        unpack2(acc[c][1], r2, r3);
        unpack2(acc[c][2], r4, r5);
        unpack2(acc[c][3], r6, r7);
        ((float4*)op)[0] = make_float4(r0, r1, r2, r3);
        ((float4*)op)[1] = make_float4(r4, r5, r6, r7);
    }
}

extern "C" void kernel_launch(void* const* d_in, const int* in_sizes, int n_in,
                              void* d_out, int out_size)
{
    const float* x = (const float*)d_in[0];
    const float* w = (const float*)d_in[1];
    float* out = (float*)d_out;

    dim3 grid(Ww / TW, Hh / TH, Bb);   // (16, 128, 8)
    conv3x3_kernel<<<grid, THREADS>>>(x, w, out);
}